// round 4
// baseline (speedup 1.0000x reference)
#include <cuda_runtime.h>
#include <cstdint>

#define B_SZ 2048
#define N_SZ 128
#define D_SZ 512
#define NT_G 256
#define NT_F 128          // fused kernel: 4 warps

typedef unsigned long long u64;

// 8 MB scratch for cw = content @ cow, row r = b*2 + k (k=0 text, k=1 img)
__device__ float g_cw[B_SZ * 2 * D_SZ];

__device__ __forceinline__ u64 pk(float lo, float hi) {
    u64 r; asm("mov.b64 %0, {%1,%2};" : "=l"(r) : "f"(lo), "f"(hi)); return r;
}
__device__ __forceinline__ void upk(u64 v, float& lo, float& hi) {
    asm("mov.b64 {%0,%1}, %2;" : "=f"(lo), "=f"(hi) : "l"(v));
}
__device__ __forceinline__ u64 fma2(u64 a, u64 b, u64 c) {
    u64 d; asm("fma.rn.f32x2 %0, %1, %2, %3;" : "=l"(d) : "l"(a), "l"(b), "l"(c)); return d;
}
__device__ __forceinline__ float hsum2(u64 v) {
    float lo, hi; upk(v, lo, hi); return lo + hi;
}
__device__ __forceinline__ float tanh_mufu(float x) {
    float y; asm("tanh.approx.f32 %0, %1;" : "=f"(y) : "f"(x)); return y;
}
__device__ __forceinline__ float tanh_precise(float x) {
    float ax = fabsf(x);
    if (ax > 15.0f) return copysignf(1.0f, x);
    float t = __expf(2.0f * x);
    return (t - 1.0f) / (t + 1.0f);
}
__device__ __forceinline__ float warp_sum(float v) {
    #pragma unroll
    for (int o = 16; o > 0; o >>= 1) v += __shfl_xor_sync(0xffffffffu, v, o);
    return v;
}

// ---------------------------------------------------------------------------
// Kernel A: cw[4096 x 512] = content[4096 x 512] @ cow[512 x 512]
// BM=BN=64, BK=16, 256 threads; FFMA2-packed 4x4 register tile.
// ---------------------------------------------------------------------------
__global__ void __launch_bounds__(NT_G) gemm_cw_kernel(
    const float* __restrict__ text, const float* __restrict__ img,
    const float* __restrict__ cow)
{
    __shared__ __align__(16) float As[16][64];
    __shared__ __align__(16) float Bs[16][64];

    const int tid  = threadIdx.x;
    const int tr   = tid >> 4;
    const int tc   = tid & 15;
    const int row0 = blockIdx.y * 64;
    const int col0 = blockIdx.x * 64;

    const int aRow = tid >> 2;
    const int aCol = (tid & 3) * 4;
    const int bRow = tid >> 4;
    const int bCol = (tid & 15) * 4;

    const int grow = row0 + aRow;
    const float* srcA = (grow & 1) ? img : text;
    const float* aPtr = srcA + (size_t)(grow >> 1) * D_SZ + aCol;

    u64 acc01[4], acc23[4];   // acc01[i] = (acc[i][0], acc[i][1]) packed
    #pragma unroll
    for (int i = 0; i < 4; i++) { acc01[i] = 0ull; acc23[i] = 0ull; }

    for (int kk = 0; kk < D_SZ; kk += 16) {
        float4 av = *(const float4*)(aPtr + kk);
        As[aCol + 0][aRow] = av.x;
        As[aCol + 1][aRow] = av.y;
        As[aCol + 2][aRow] = av.z;
        As[aCol + 3][aRow] = av.w;
        *(float4*)&Bs[bRow][bCol] =
            *(const float4*)(cow + (size_t)(kk + bRow) * D_SZ + col0 + bCol);
        __syncthreads();

        #pragma unroll
        for (int k = 0; k < 16; k++) {
            float4 a4 = *(const float4*)&As[k][tr * 4];
            ulonglong2 b2 = *(const ulonglong2*)&Bs[k][tc * 4];
            float ar[4] = {a4.x, a4.y, a4.z, a4.w};
            #pragma unroll
            for (int i = 0; i < 4; i++) {
                u64 ai = pk(ar[i], ar[i]);
                acc01[i] = fma2(ai, b2.x, acc01[i]);
                acc23[i] = fma2(ai, b2.y, acc23[i]);
            }
        }
        __syncthreads();
    }

    #pragma unroll
    for (int i = 0; i < 4; i++) {
        float4 v;
        upk(acc01[i], v.x, v.y);
        upk(acc23[i], v.z, v.w);
        *(float4*)(g_cw + (size_t)(row0 + tr * 4 + i) * D_SZ + col0 + tc * 4) = v;
    }
}

// ---------------------------------------------------------------------------
// Kernel B v3: warp-per-row-pair, register-resident z, FFMA2 throughout.
// One CTA (4 warps) per batch element.
// ---------------------------------------------------------------------------
__global__ void __launch_bounds__(NT_F, 4) fused_kernel(
    const float* __restrict__ text, const float* __restrict__ img,
    const float* __restrict__ comment, const int* __restrict__ comment_num,
    const float* __restrict__ W_ca, const float* __restrict__ b_ca,
    const float* __restrict__ W_co, const float* __restrict__ b_co,
    float* __restrict__ out)
{
    __shared__ __align__(16) float cwS[2 * D_SZ];
    __shared__ __align__(16) float ccS[2 * D_SZ];
    __shared__ __align__(16) float wcoS[D_SZ];
    __shared__ __align__(16) float wcaS[D_SZ];
    __shared__ __align__(16) float redS[3 * 4 * D_SZ];
    __shared__ float ssumS[4];
    __shared__ float pS[8];

    const int b    = blockIdx.x;
    const int tid  = threadIdx.x;
    const int lane = tid & 31;
    const int w    = tid >> 5;
    const int M    = comment_num[b];

    for (int i = tid; i < 2 * D_SZ / 4; i += NT_F)
        ((float4*)cwS)[i] = ((const float4*)(g_cw + (size_t)b * 2 * D_SZ))[i];
    for (int i = tid; i < D_SZ / 4; i += NT_F) {
        ((float4*)ccS)[i]          = ((const float4*)(text + (size_t)b * D_SZ))[i];
        ((float4*)(ccS + D_SZ))[i] = ((const float4*)(img  + (size_t)b * D_SZ))[i];
        ((float4*)wcoS)[i]         = ((const float4*)W_co)[i];
        ((float4*)wcaS)[i]         = ((const float4*)W_ca)[i];
    }
    __syncthreads();

    const float bco = b_co[0];

    const ulonglong2* cw0_2 = (const ulonglong2*)cwS;
    const ulonglong2* cw1_2 = (const ulonglong2*)(cwS + D_SZ);
    const ulonglong2* c0_2  = (const ulonglong2*)ccS;
    const ulonglong2* c1_2  = (const ulonglong2*)(ccS + D_SZ);
    const ulonglong2* wco_2 = (const ulonglong2*)wcoS;

    u64 accp[8], s0p[8], s1p[8];
    #pragma unroll
    for (int j = 0; j < 8; j++) { accp[j] = 0ull; s0p[j] = 0ull; s1p[j] = 0ull; }
    float ssum = 0.f;

    const int npairs = (M + 1) >> 1;
    for (int p = w; p < npairs; p += 4) {
        const int n0 = 2 * p;
        const bool v1 = (n0 + 1) < M;
        const ulonglong2* z0g = (const ulonglong2*)(comment + ((size_t)b * N_SZ + n0) * D_SZ);
        const ulonglong2* z1g = z0g + D_SZ / 4;

        ulonglong2 z0v[4], z1v[4];
        #pragma unroll
        for (int j = 0; j < 4; j++) z0v[j] = z0g[lane + 32 * j];
        if (v1) {
            #pragma unroll
            for (int j = 0; j < 4; j++) z1v[j] = z1g[lane + 32 * j];
        } else {
            #pragma unroll
            for (int j = 0; j < 4; j++) z1v[j] = make_ulonglong2(0ull, 0ull);
        }

        // --- co_w dots: a_rk = cw_k . z_r (packed) ---
        u64 pa00 = 0ull, pa01 = 0ull, pa10 = 0ull, pa11 = 0ull;
        #pragma unroll
        for (int j = 0; j < 4; j++) {
            ulonglong2 ca = cw0_2[lane + 32 * j];
            ulonglong2 cb = cw1_2[lane + 32 * j];
            pa00 = fma2(z0v[j].x, ca.x, pa00); pa00 = fma2(z0v[j].y, ca.y, pa00);
            pa01 = fma2(z0v[j].x, cb.x, pa01); pa01 = fma2(z0v[j].y, cb.y, pa01);
            pa10 = fma2(z1v[j].x, ca.x, pa10); pa10 = fma2(z1v[j].y, ca.y, pa10);
            pa11 = fma2(z1v[j].x, cb.x, pa11); pa11 = fma2(z1v[j].y, cb.y, pa11);
        }
        float a00 = warp_sum(hsum2(pa00));
        float a01 = warp_sum(hsum2(pa01));
        float a10 = warp_sum(hsum2(pa10));
        float a11 = warp_sum(hsum2(pa11));
        const float w00 = tanh_precise(a00);
        const float w01 = tanh_precise(a01);
        const float w10 = tanh_precise(a10);
        const float w11 = tanh_precise(a11);
        const u64 pw00 = pk(w00, w00), pw01 = pk(w01, w01);
        const u64 pw10 = pk(w10, w10), pw11 = pk(w11, w11);

        // --- zw logits: lam_r = sum_d tanh(z + w_r0*c0 + w_r1*c1) * W_co ---
        u64 pl0 = 0ull, pl1 = 0ull;
        #pragma unroll
        for (int j = 0; j < 4; j++) {
            ulonglong2 u0 = c0_2[lane + 32 * j];
            ulonglong2 u1 = c1_2[lane + 32 * j];
            ulonglong2 wv = wco_2[lane + 32 * j];
            float lo, hi;
            u64 t;
            t = fma2(pw00, u0.x, z0v[j].x); t = fma2(pw01, u1.x, t);
            upk(t, lo, hi);
            pl0 = fma2(pk(tanh_mufu(lo), tanh_mufu(hi)), wv.x, pl0);
            t = fma2(pw00, u0.y, z0v[j].y); t = fma2(pw01, u1.y, t);
            upk(t, lo, hi);
            pl0 = fma2(pk(tanh_mufu(lo), tanh_mufu(hi)), wv.y, pl0);
            t = fma2(pw10, u0.x, z1v[j].x); t = fma2(pw11, u1.x, t);
            upk(t, lo, hi);
            pl1 = fma2(pk(tanh_mufu(lo), tanh_mufu(hi)), wv.x, pl1);
            t = fma2(pw10, u0.y, z1v[j].y); t = fma2(pw11, u1.y, t);
            upk(t, lo, hi);
            pl1 = fma2(pk(tanh_mufu(lo), tanh_mufu(hi)), wv.y, pl1);
        }
        float l0 = warp_sum(hsum2(pl0));
        float l1 = warp_sum(hsum2(pl1));

        // logits bounded by sum|W_co| (~18): exp without max-shift is safe
        const float e0 = __expf(l0 + bco);
        const float e1 = v1 ? __expf(l1 + bco) : 0.f;
        ssum += e0 + e1;
        const u64 pe0 = pk(e0, e0), pe1 = pk(e1, e1);

        // --- accumulate softmax numerator and s_k vectors (packed) ---
        #pragma unroll
        for (int j = 0; j < 4; j++) {
            accp[2*j]   = fma2(pe0, z0v[j].x, accp[2*j]);
            accp[2*j]   = fma2(pe1, z1v[j].x, accp[2*j]);
            accp[2*j+1] = fma2(pe0, z0v[j].y, accp[2*j+1]);
            accp[2*j+1] = fma2(pe1, z1v[j].y, accp[2*j+1]);
            s0p[2*j]    = fma2(pw00, z0v[j].x, s0p[2*j]);
            s0p[2*j]    = fma2(pw10, z1v[j].x, s0p[2*j]);
            s0p[2*j+1]  = fma2(pw00, z0v[j].y, s0p[2*j+1]);
            s0p[2*j+1]  = fma2(pw10, z1v[j].y, s0p[2*j+1]);
            s1p[2*j]    = fma2(pw01, z0v[j].x, s1p[2*j]);
            s1p[2*j]    = fma2(pw11, z1v[j].x, s1p[2*j]);
            s1p[2*j+1]  = fma2(pw01, z0v[j].y, s1p[2*j+1]);
            s1p[2*j+1]  = fma2(pw11, z1v[j].y, s1p[2*j+1]);
        }
    }

    // --- cross-warp merge (same float4 slot layout as before) ---
    #pragma unroll
    for (int j = 0; j < 4; j++) {
        const int idx = w * 128 + lane + 32 * j;
        ((ulonglong2*)redS)[idx]        = make_ulonglong2(accp[2*j], accp[2*j+1]);
        ((ulonglong2*)redS)[512 + idx]  = make_ulonglong2(s0p[2*j],  s0p[2*j+1]);
        ((ulonglong2*)redS)[1024 + idx] = make_ulonglong2(s1p[2*j],  s1p[2*j+1]);
    }
    if (lane == 0) ssumS[w] = ssum;
    __syncthreads();

    float4 A  = make_float4(0.f, 0.f, 0.f, 0.f);
    float4 S0 = make_float4(0.f, 0.f, 0.f, 0.f);
    float4 S1 = make_float4(0.f, 0.f, 0.f, 0.f);
    #pragma unroll
    for (int ww = 0; ww < 4; ww++) {
        float4 a = ((float4*)redS)[ww * 128 + tid];
        float4 x = ((float4*)redS)[512 + ww * 128 + tid];
        float4 y = ((float4*)redS)[1024 + ww * 128 + tid];
        A.x += a.x; A.y += a.y; A.z += a.z; A.w += a.w;
        S0.x += x.x; S0.y += x.y; S0.z += x.z; S0.w += x.w;
        S1.x += y.x; S1.y += y.y; S1.z += y.z; S1.w += y.w;
    }
    const float stot = ssumS[0] + ssumS[1] + ssumS[2] + ssumS[3];
    const float inv = 1.0f / stot;

    float* out_rcontent = out;
    float* out_rcomment = out + (size_t)B_SZ * D_SZ;
    float* out_contentw = out + (size_t)2 * B_SZ * D_SZ;

    ((float4*)out_rcomment)[(size_t)b * 128 + tid] =
        make_float4(A.x * inv, A.y * inv, A.z * inv, A.w * inv);

    float4 c0q = ((const float4*)ccS)[tid];
    float4 c1q = ((const float4*)(ccS + D_SZ))[tid];
    float4 waq = ((const float4*)wcaS)[tid];
    float p0 = tanh_mufu(c0q.x + S0.x) * waq.x + tanh_mufu(c0q.y + S0.y) * waq.y
             + tanh_mufu(c0q.z + S0.z) * waq.z + tanh_mufu(c0q.w + S0.w) * waq.w;
    float p1 = tanh_mufu(c1q.x + S1.x) * waq.x + tanh_mufu(c1q.y + S1.y) * waq.y
             + tanh_mufu(c1q.z + S1.z) * waq.z + tanh_mufu(c1q.w + S1.w) * waq.w;
    p0 = warp_sum(p0);
    p1 = warp_sum(p1);
    if (lane == 0) { pS[w] = p0; pS[4 + w] = p1; }
    __syncthreads();
    const float bca = b_ca[0];
    const float l0 = pS[0] + pS[1] + pS[2] + pS[3] + bca;
    const float l1 = pS[4] + pS[5] + pS[6] + pS[7] + bca;

    const float mx = fmaxf(l0, l1);
    const float e0 = __expf(l0 - mx), e1 = __expf(l1 - mx);
    const float is = 1.0f / (e0 + e1);
    const float q0 = e0 * is, q1 = e1 * is;

    if (tid == 0) {
        out_contentw[(size_t)b * 2 + 0] = q0;
        out_contentw[(size_t)b * 2 + 1] = q1;
    }
    ((float4*)out_rcontent)[(size_t)b * 128 + tid] =
        make_float4(c0q.x * q0 + c1q.x * q1, c0q.y * q0 + c1q.y * q1,
                    c0q.z * q0 + c1q.z * q1, c0q.w * q0 + c1q.w * q1);
}

// ---------------------------------------------------------------------------
extern "C" void kernel_launch(void* const* d_in, const int* in_sizes, int n_in,
                              void* d_out, int out_size)
{
    const float* text        = (const float*)d_in[0];
    const float* img         = (const float*)d_in[1];
    const float* comment     = (const float*)d_in[2];
    const int*   comment_num = (const int*)  d_in[3];
    const float* cow         = (const float*)d_in[4];
    const float* W_ca        = (const float*)d_in[5];
    const float* b_ca        = (const float*)d_in[6];
    const float* W_co        = (const float*)d_in[7];
    const float* b_co        = (const float*)d_in[8];
    float* out = (float*)d_out;

    dim3 gA(D_SZ / 64, (B_SZ * 2) / 64);   // (8, 64)
    gemm_cw_kernel<<<gA, NT_G>>>(text, img, cow);

    fused_kernel<<<B_SZ, NT_F>>>(text, img, comment, comment_num,
                                 W_ca, b_ca, W_co, b_co, out);
}

// round 6
// speedup vs baseline: 1.7949x; 1.7949x over previous
#include <cuda_runtime.h>
#include <cuda_bf16.h>
#include <mma.h>
#include <cstdint>

#define B_SZ 2048
#define N_SZ 128
#define D_SZ 512
#define NT_F 128

using namespace nvcuda;

// scratch: cw = content @ cow (fp32), plus bf16 split operands
__device__ float g_cw[B_SZ * 2 * D_SZ];                      // 8 MB
__device__ __nv_bfloat16 g_a_hi[B_SZ * 2 * D_SZ];            // 4 MB
__device__ __nv_bfloat16 g_a_lo[B_SZ * 2 * D_SZ];            // 4 MB
__device__ __nv_bfloat16 g_b_hi[D_SZ * D_SZ];                // 0.5 MB (cow, [k][n])
__device__ __nv_bfloat16 g_b_lo[D_SZ * D_SZ];                // 0.5 MB

__device__ __forceinline__ float tanh_mufu(float x) {
    float y; asm("tanh.approx.f32 %0, %1;" : "=f"(y) : "f"(x)); return y;
}
__device__ __forceinline__ float tanh_precise(float x) {
    float ax = fabsf(x);
    if (ax > 15.0f) return copysignf(1.0f, x);
    float t = __expf(2.0f * x);
    return (t - 1.0f) / (t + 1.0f);
}
__device__ __forceinline__ float warp_sum(float v) {
    #pragma unroll
    for (int o = 16; o > 0; o >>= 1) v += __shfl_xor_sync(0xffffffffu, v, o);
    return v;
}

// ======================= prep kernels =======================
// content rows m = 2b+k split to bf16 hi/lo
__global__ void __launch_bounds__(256) prep_content_kernel(
    const float* __restrict__ text, const float* __restrict__ img)
{
    int idx = blockIdx.x * 256 + threadIdx.x;      // float4 id, total 512K
    int m  = idx >> 7;
    int d4 = idx & 127;
    const float* src = (m & 1) ? img : text;
    float4 v = ((const float4*)(src + (size_t)(m >> 1) * D_SZ))[d4];
    float xs[4] = {v.x, v.y, v.z, v.w};
    __nv_bfloat16 hi[4], lo[4];
    #pragma unroll
    for (int i = 0; i < 4; i++) {
        hi[i] = __float2bfloat16(xs[i]);
        lo[i] = __float2bfloat16(xs[i] - __bfloat162float(hi[i]));
    }
    __nv_bfloat162* ph = (__nv_bfloat162*)g_a_hi;
    __nv_bfloat162* pl = (__nv_bfloat162*)g_a_lo;
    ph[idx * 2]     = __nv_bfloat162(hi[0], hi[1]);
    ph[idx * 2 + 1] = __nv_bfloat162(hi[2], hi[3]);
    pl[idx * 2]     = __nv_bfloat162(lo[0], lo[1]);
    pl[idx * 2 + 1] = __nv_bfloat162(lo[2], lo[3]);
}

// cow [k][n] row-major split to bf16 hi/lo (no transpose: matches wmma matrix_b row_major)
__global__ void __launch_bounds__(256) prep_cow_kernel(const float* __restrict__ cow)
{
    int idx = blockIdx.x * 256 + threadIdx.x;      // float4 id, total 64K
    float4 v = ((const float4*)cow)[idx];
    float xs[4] = {v.x, v.y, v.z, v.w};
    __nv_bfloat16 hi[4], lo[4];
    #pragma unroll
    for (int i = 0; i < 4; i++) {
        hi[i] = __float2bfloat16(xs[i]);
        lo[i] = __float2bfloat16(xs[i] - __bfloat162float(hi[i]));
    }
    __nv_bfloat162* ph = (__nv_bfloat162*)g_b_hi;
    __nv_bfloat162* pl = (__nv_bfloat162*)g_b_lo;
    ph[idx * 2]     = __nv_bfloat162(hi[0], hi[1]);
    ph[idx * 2 + 1] = __nv_bfloat162(hi[2], hi[3]);
    pl[idx * 2]     = __nv_bfloat162(lo[0], lo[1]);
    pl[idx * 2 + 1] = __nv_bfloat162(lo[2], lo[3]);
}

// ======================= wmma bf16 split GEMM =======================
// cw[4096 x 512] = A[4096 x 512] @ B[512 x 512]; 3 split terms.
// BM=64, BN=128, BK=32; 8 warps, each a 32x32 tile (2x2 wmma frags).
#define GA_LD 40
#define GB_LD 136
__global__ void __launch_bounds__(256) gemm_wmma_kernel()
{
    __shared__ __nv_bfloat16 sAhi[64][GA_LD];
    __shared__ __nv_bfloat16 sAlo[64][GA_LD];
    __shared__ __nv_bfloat16 sBhi[32][GB_LD];
    __shared__ __nv_bfloat16 sBlo[32][GB_LD];

    const int tid  = threadIdx.x;
    const int w    = tid >> 5;
    const int wm   = w >> 2;            // 0..1
    const int wn   = w & 3;             // 0..3
    const int row0 = blockIdx.y * 64;
    const int col0 = blockIdx.x * 128;

    wmma::fragment<wmma::accumulator, 16, 16, 16, float> acc[2][2];
    #pragma unroll
    for (int i = 0; i < 2; i++)
        #pragma unroll
        for (int j = 0; j < 2; j++) wmma::fill_fragment(acc[i][j], 0.0f);

    // A tile: 64x32, one uint4 (8 bf16) per thread
    const int aRow = tid >> 2;
    const int aC8  = (tid & 3) * 8;
    // B tile: 32x128, two uint4 per thread
    for (int kk = 0; kk < D_SZ; kk += 32) {
        *(uint4*)&sAhi[aRow][aC8] =
            *(const uint4*)(g_a_hi + (size_t)(row0 + aRow) * D_SZ + kk + aC8);
        *(uint4*)&sAlo[aRow][aC8] =
            *(const uint4*)(g_a_lo + (size_t)(row0 + aRow) * D_SZ + kk + aC8);
        #pragma unroll
        for (int it = 0; it < 2; it++) {
            int s    = tid + it * 256;
            int bRow = s >> 4;
            int bC8  = (s & 15) * 8;
            *(uint4*)&sBhi[bRow][bC8] =
                *(const uint4*)(g_b_hi + (size_t)(kk + bRow) * D_SZ + col0 + bC8);
            *(uint4*)&sBlo[bRow][bC8] =
                *(const uint4*)(g_b_lo + (size_t)(kk + bRow) * D_SZ + col0 + bC8);
        }
        __syncthreads();

        #pragma unroll
        for (int ks = 0; ks < 32; ks += 16) {
            wmma::fragment<wmma::matrix_a, 16, 16, 16, __nv_bfloat16, wmma::row_major> aH[2], aL[2];
            wmma::fragment<wmma::matrix_b, 16, 16, 16, __nv_bfloat16, wmma::row_major> bH[2], bL[2];
            #pragma unroll
            for (int i = 0; i < 2; i++) {
                wmma::load_matrix_sync(aH[i], &sAhi[wm * 32 + i * 16][ks], GA_LD);
                wmma::load_matrix_sync(aL[i], &sAlo[wm * 32 + i * 16][ks], GA_LD);
            }
            #pragma unroll
            for (int j = 0; j < 2; j++) {
                wmma::load_matrix_sync(bH[j], &sBhi[ks][wn * 32 + j * 16], GB_LD);
                wmma::load_matrix_sync(bL[j], &sBlo[ks][wn * 32 + j * 16], GB_LD);
            }
            #pragma unroll
            for (int i = 0; i < 2; i++)
                #pragma unroll
                for (int j = 0; j < 2; j++) {
                    wmma::mma_sync(acc[i][j], aH[i], bH[j], acc[i][j]);
                    wmma::mma_sync(acc[i][j], aH[i], bL[j], acc[i][j]);
                    wmma::mma_sync(acc[i][j], aL[i], bH[j], acc[i][j]);
                }
        }
        __syncthreads();
    }

    #pragma unroll
    for (int i = 0; i < 2; i++)
        #pragma unroll
        for (int j = 0; j < 2; j++)
            wmma::store_matrix_sync(
                g_cw + (size_t)(row0 + wm * 32 + i * 16) * D_SZ + col0 + wn * 32 + j * 16,
                acc[i][j], D_SZ, wmma::mem_row_major);
}

// ======================= fused kernel (R3, measured 101 us) =======================
__global__ void __launch_bounds__(NT_F, 4) fused_kernel(
    const float* __restrict__ text, const float* __restrict__ img,
    const float* __restrict__ comment, const int* __restrict__ comment_num,
    const float* __restrict__ W_ca, const float* __restrict__ b_ca,
    const float* __restrict__ W_co, const float* __restrict__ b_co,
    float* __restrict__ out)
{
    __shared__ float cwS[2 * D_SZ];
    __shared__ float ccS[2 * D_SZ];
    __shared__ float wcoS[D_SZ];
    __shared__ float wcaS[D_SZ];
    __shared__ float redS[3 * 4 * D_SZ];
    __shared__ float ssumS[4];
    __shared__ float pS[8];

    const int b    = blockIdx.x;
    const int tid  = threadIdx.x;
    const int lane = tid & 31;
    const int w    = tid >> 5;
    const int M    = comment_num[b];

    for (int i = tid; i < 2 * D_SZ / 4; i += NT_F)
        ((float4*)cwS)[i] = ((const float4*)(g_cw + (size_t)b * 2 * D_SZ))[i];
    for (int i = tid; i < D_SZ / 4; i += NT_F) {
        ((float4*)ccS)[i]          = ((const float4*)(text + (size_t)b * D_SZ))[i];
        ((float4*)(ccS + D_SZ))[i] = ((const float4*)(img  + (size_t)b * D_SZ))[i];
        ((float4*)wcoS)[i]         = ((const float4*)W_co)[i];
        ((float4*)wcaS)[i]         = ((const float4*)W_ca)[i];
    }
    __syncthreads();

    const float bco = b_co[0];

    const float4* cw04 = (const float4*)cwS;
    const float4* cw14 = (const float4*)(cwS + D_SZ);
    const float4* c04  = (const float4*)ccS;
    const float4* c14  = (const float4*)(ccS + D_SZ);
    const float4* wco4 = (const float4*)wcoS;

    float4 acc[4], s0[4], s1[4];
    #pragma unroll
    for (int j = 0; j < 4; j++) {
        acc[j] = make_float4(0.f, 0.f, 0.f, 0.f);
        s0[j]  = make_float4(0.f, 0.f, 0.f, 0.f);
        s1[j]  = make_float4(0.f, 0.f, 0.f, 0.f);
    }
    float ssum = 0.f;

    const int npairs = (M + 1) >> 1;
    for (int p = w; p < npairs; p += 4) {
        const int n0 = 2 * p;
        const bool v1 = (n0 + 1) < M;
        const float4* z0p = (const float4*)(comment + ((size_t)b * N_SZ + n0) * D_SZ);
        const float4* z1p = z0p + D_SZ / 4;

        float4 z0[4], z1[4];
        #pragma unroll
        for (int j = 0; j < 4; j++) z0[j] = z0p[lane + 32 * j];
        if (v1) {
            #pragma unroll
            for (int j = 0; j < 4; j++) z1[j] = z1p[lane + 32 * j];
        } else {
            #pragma unroll
            for (int j = 0; j < 4; j++) z1[j] = make_float4(0.f, 0.f, 0.f, 0.f);
        }

        float a00 = 0.f, a01 = 0.f, a10 = 0.f, a11 = 0.f;
        #pragma unroll
        for (int j = 0; j < 4; j++) {
            float4 ca = cw04[lane + 32 * j];
            float4 cb = cw14[lane + 32 * j];
            a00 = fmaf(z0[j].x, ca.x, fmaf(z0[j].y, ca.y, fmaf(z0[j].z, ca.z, fmaf(z0[j].w, ca.w, a00))));
            a01 = fmaf(z0[j].x, cb.x, fmaf(z0[j].y, cb.y, fmaf(z0[j].z, cb.z, fmaf(z0[j].w, cb.w, a01))));
            a10 = fmaf(z1[j].x, ca.x, fmaf(z1[j].y, ca.y, fmaf(z1[j].z, ca.z, fmaf(z1[j].w, ca.w, a10))));
            a11 = fmaf(z1[j].x, cb.x, fmaf(z1[j].y, cb.y, fmaf(z1[j].z, cb.z, fmaf(z1[j].w, cb.w, a11))));
        }
        a00 = warp_sum(a00); a01 = warp_sum(a01);
        a10 = warp_sum(a10); a11 = warp_sum(a11);
        const float w00 = tanh_precise(a00);
        const float w01 = tanh_precise(a01);
        const float w10 = tanh_precise(a10);
        const float w11 = tanh_precise(a11);

        float l0 = 0.f, l1 = 0.f;
        #pragma unroll
        for (int j = 0; j < 4; j++) {
            float4 u0 = c04[lane + 32 * j];
            float4 u1 = c14[lane + 32 * j];
            float4 wv = wco4[lane + 32 * j];
            l0 = fmaf(tanh_mufu(fmaf(w00, u0.x, fmaf(w01, u1.x, z0[j].x))), wv.x, l0);
            l0 = fmaf(tanh_mufu(fmaf(w00, u0.y, fmaf(w01, u1.y, z0[j].y))), wv.y, l0);
            l0 = fmaf(tanh_mufu(fmaf(w00, u0.z, fmaf(w01, u1.z, z0[j].z))), wv.z, l0);
            l0 = fmaf(tanh_mufu(fmaf(w00, u0.w, fmaf(w01, u1.w, z0[j].w))), wv.w, l0);
            l1 = fmaf(tanh_mufu(fmaf(w10, u0.x, fmaf(w11, u1.x, z1[j].x))), wv.x, l1);
            l1 = fmaf(tanh_mufu(fmaf(w10, u0.y, fmaf(w11, u1.y, z1[j].y))), wv.y, l1);
            l1 = fmaf(tanh_mufu(fmaf(w10, u0.z, fmaf(w11, u1.z, z1[j].z))), wv.z, l1);
            l1 = fmaf(tanh_mufu(fmaf(w10, u0.w, fmaf(w11, u1.w, z1[j].w))), wv.w, l1);
        }
        l0 = warp_sum(l0);
        l1 = warp_sum(l1);

        const float e0 = __expf(l0 + bco);
        const float e1 = v1 ? __expf(l1 + bco) : 0.f;
        ssum += e0 + e1;

        #pragma unroll
        for (int j = 0; j < 4; j++) {
            acc[j].x = fmaf(e0, z0[j].x, fmaf(e1, z1[j].x, acc[j].x));
            acc[j].y = fmaf(e0, z0[j].y, fmaf(e1, z1[j].y, acc[j].y));
            acc[j].z = fmaf(e0, z0[j].z, fmaf(e1, z1[j].z, acc[j].z));
            acc[j].w = fmaf(e0, z0[j].w, fmaf(e1, z1[j].w, acc[j].w));
            s0[j].x  = fmaf(w00, z0[j].x, fmaf(w10, z1[j].x, s0[j].x));
            s0[j].y  = fmaf(w00, z0[j].y, fmaf(w10, z1[j].y, s0[j].y));
            s0[j].z  = fmaf(w00, z0[j].z, fmaf(w10, z1[j].z, s0[j].z));
            s0[j].w  = fmaf(w00, z0[j].w, fmaf(w10, z1[j].w, s0[j].w));
            s1[j].x  = fmaf(w01, z0[j].x, fmaf(w11, z1[j].x, s1[j].x));
            s1[j].y  = fmaf(w01, z0[j].y, fmaf(w11, z1[j].y, s1[j].y));
            s1[j].z  = fmaf(w01, z0[j].z, fmaf(w11, z1[j].z, s1[j].z));
            s1[j].w  = fmaf(w01, z0[j].w, fmaf(w11, z1[j].w, s1[j].w));
        }
    }

    #pragma unroll
    for (int j = 0; j < 4; j++) {
        const int idx = w * 128 + lane + 32 * j;
        ((float4*)redS)[idx]        = acc[j];
        ((float4*)redS)[512 + idx]  = s0[j];
        ((float4*)redS)[1024 + idx] = s1[j];
    }
    if (lane == 0) ssumS[w] = ssum;
    __syncthreads();

    float4 A  = make_float4(0.f, 0.f, 0.f, 0.f);
    float4 S0 = make_float4(0.f, 0.f, 0.f, 0.f);
    float4 S1 = make_float4(0.f, 0.f, 0.f, 0.f);
    #pragma unroll
    for (int ww = 0; ww < 4; ww++) {
        float4 a = ((float4*)redS)[ww * 128 + tid];
        float4 x = ((float4*)redS)[512 + ww * 128 + tid];
        float4 y = ((float4*)redS)[1024 + ww * 128 + tid];
        A.x += a.x; A.y += a.y; A.z += a.z; A.w += a.w;
        S0.x += x.x; S0.y += x.y; S0.z += x.z; S0.w += x.w;
        S1.x += y.x; S1.y += y.y; S1.z += y.z; S1.w += y.w;
    }
    const float stot = ssumS[0] + ssumS[1] + ssumS[2] + ssumS[3];
    const float inv = 1.0f / stot;

    float* out_rcontent = out;
    float* out_rcomment = out + (size_t)B_SZ * D_SZ;
    float* out_contentw = out + (size_t)2 * B_SZ * D_SZ;

    ((float4*)out_rcomment)[(size_t)b * 128 + tid] =
        make_float4(A.x * inv, A.y * inv, A.z * inv, A.w * inv);

    float4 c0q = c04[tid], c1q = c14[tid], waq = ((const float4*)wcaS)[tid];
    float p0 = tanh_mufu(c0q.x + S0.x) * waq.x + tanh_mufu(c0q.y + S0.y) * waq.y
             + tanh_mufu(c0q.z + S0.z) * waq.z + tanh_mufu(c0q.w + S0.w) * waq.w;
    float p1 = tanh_mufu(c1q.x + S1.x) * waq.x + tanh_mufu(c1q.y + S1.y) * waq.y
             + tanh_mufu(c1q.z + S1.z) * waq.z + tanh_mufu(c1q.w + S1.w) * waq.w;
    p0 = warp_sum(p0);
    p1 = warp_sum(p1);
    if (lane == 0) { pS[w] = p0; pS[4 + w] = p1; }
    __syncthreads();
    const float bca = b_ca[0];
    const float l0 = pS[0] + pS[1] + pS[2] + pS[3] + bca;
    const float l1 = pS[4] + pS[5] + pS[6] + pS[7] + bca;

    const float mx = fmaxf(l0, l1);
    const float e0 = __expf(l0 - mx), e1 = __expf(l1 - mx);
    const float is = 1.0f / (e0 + e1);
    const float q0 = e0 * is, q1 = e1 * is;

    if (tid == 0) {
        out_contentw[(size_t)b * 2 + 0] = q0;
        out_contentw[(size_t)b * 2 + 1] = q1;
    }
    ((float4*)out_rcontent)[(size_t)b * 128 + tid] =
        make_float4(c0q.x * q0 + c1q.x * q1, c0q.y * q0 + c1q.y * q1,
                    c0q.z * q0 + c1q.z * q1, c0q.w * q0 + c1q.w * q1);
}

// ---------------------------------------------------------------------------
extern "C" void kernel_launch(void* const* d_in, const int* in_sizes, int n_in,
                              void* d_out, int out_size)
{
    const float* text        = (const float*)d_in[0];
    const float* img         = (const float*)d_in[1];
    const float* comment     = (const float*)d_in[2];
    const int*   comment_num = (const int*)  d_in[3];
    const float* cow         = (const float*)d_in[4];
    const float* W_ca        = (const float*)d_in[5];
    const float* b_ca        = (const float*)d_in[6];
    const float* W_co        = (const float*)d_in[7];
    const float* b_co        = (const float*)d_in[8];
    float* out = (float*)d_out;

    prep_content_kernel<<<2048, 256>>>(text, img);
    prep_cow_kernel<<<256, 256>>>(cow);

    dim3 gG(D_SZ / 128, (B_SZ * 2) / 64);   // (4, 64)
    gemm_wmma_kernel<<<gG, 256>>>();

    fused_kernel<<<B_SZ, NT_F>>>(text, img, comment, comment_num,
                                 W_ca, b_ca, W_co, b_co, out);
}